// round 1
// baseline (speedup 1.0000x reference)
#include <cuda_runtime.h>
#include <cuda_bf16.h>

#define NN 8192
#define IND 512
#define DD 64
#define ALPHA 0.2f

// attention tiling
#define BI 256       // rows per block
#define BJ 32        // j per tile
#define JS 4         // j splits
#define JLEN (NN/JS) // 2048
#define NT (JLEN/BJ) // 64 tiles

// -------- device scratch (no allocation allowed) --------
__device__ __align__(16) float g_h[NN*DD];        // 2 MB
__device__ __align__(16) float g_h1[NN];
__device__ __align__(16) float g_h2[NN];
__device__ __align__(16) float g_acc[(size_t)JS*NN*DD]; // 8 MB
__device__ __align__(16) float g_Z[JS*NN];

// ---------------- kernel 1: h = X @ W  (8192x512 @ 512x64) ----------------
__global__ void __launch_bounds__(256) gemm_h_kernel(const float* __restrict__ X,
                                                     const float* __restrict__ W) {
    __shared__ float xs[16][IND];   // 32 KB
    const int tid = threadIdx.x;
    const int row0 = blockIdx.x * 16;

    // cooperative load of 16 rows of X (coalesced float4)
    {
        const float4* src = (const float4*)(X + (size_t)row0 * IND);
        float4* dst = (float4*)&xs[0][0];
        #pragma unroll
        for (int i = 0; i < 8; i++) dst[tid + i*256] = src[tid + i*256];
    }
    __syncthreads();

    const int c  = tid & 63;     // output column
    const int rg = tid >> 6;     // row group 0..3 -> rows rg*4..rg*4+3
    float a0 = 0.f, a1 = 0.f, a2 = 0.f, a3 = 0.f;
    #pragma unroll 4
    for (int k = 0; k < IND; k++) {
        const float w = W[k*DD + c];           // coalesced, L2-resident (128 KB)
        a0 += xs[rg*4+0][k] * w;               // all-lane broadcast LDS
        a1 += xs[rg*4+1][k] * w;
        a2 += xs[rg*4+2][k] * w;
        a3 += xs[rg*4+3][k] * w;
    }
    g_h[(row0 + rg*4+0)*DD + c] = a0;
    g_h[(row0 + rg*4+1)*DD + c] = a1;
    g_h[(row0 + rg*4+2)*DD + c] = a2;
    g_h[(row0 + rg*4+3)*DD + c] = a3;
}

// ---------------- kernel 2: h1 = h@a[:64], h2 = h@a[64:] ----------------
__global__ void __launch_bounds__(256) proj_kernel(const float* __restrict__ a) {
    const int w = threadIdx.x >> 5, lane = threadIdx.x & 31;
    const int row = blockIdx.x * 8 + w;
    const float x0 = g_h[row*DD + lane];
    const float x1 = g_h[row*DD + 32 + lane];
    float s1 = x0 * a[lane]      + x1 * a[lane + 32];
    float s2 = x0 * a[64 + lane] + x1 * a[96 + lane];
    #pragma unroll
    for (int o = 16; o > 0; o >>= 1) {
        s1 += __shfl_xor_sync(0xffffffffu, s1, o);
        s2 += __shfl_xor_sync(0xffffffffu, s2, o);
    }
    if (lane == 0) { g_h1[row] = s1; g_h2[row] = s2; }
}

// ---------------- kernel 3: fused masked-softmax attention (partial over j-split) ----
// grid (JS, NN/BI), 256 threads. No max-subtraction needed: |scores| small enough
// for fp32 exp; masked entries contribute exactly 0 (same as reference's exp(-9e15-m)).
__global__ void __launch_bounds__(256, 1) attn_kernel(const int* __restrict__ adj) {
    __shared__ float h1s[BI];                      // 1 KB
    __shared__ float ps[BI][BJ + 1];               // 33.8 KB, pad -> conflict-free
    __shared__ __align__(16) float hts[BJ * DD];   // 8 KB

    const int tid = threadIdx.x, lane = tid & 31, w = tid >> 5;
    const int ib = blockIdx.y, js = blockIdx.x;
    const int row0 = ib * BI;
    const int jbase = js * JLEN;

    h1s[tid] = g_h1[row0 + tid];

    unsigned long long acc[32];                    // 8 rows x 8 cols as f32x2 pairs
    #pragma unroll
    for (int i = 0; i < 32; i++) acc[i] = 0ull;
    float zacc = 0.f;

    const int rg = tid >> 3, cg = tid & 7;         // PV thread tile: 8 rows x 8 cols
    const int r0 = rg * 8, c0 = cg * 8;
    const int rowb = w * 32;                       // phase-A: warp owns 32 rows

    __syncthreads();

    for (int t = 0; t < NT; t++) {
        const int j0 = jbase + t * BJ;

        // stage h tile [BJ][64] (contiguous copy, L2 hits)
        {
            const float4* src = (const float4*)(g_h + j0 * DD);
            float4* dst = (float4*)hts;
            dst[tid]       = src[tid];
            dst[tid + 256] = src[tid + 256];
        }

        // ---- phase A: p = adj ? exp(leaky(h1_i + h2_j)) : 0 -> ps[row][j] ----
        const int myj = j0 + lane;
        const float h2v = g_h2[myj];
        #pragma unroll 1
        for (int rr8 = 0; rr8 < 32; rr8 += 8) {
            int av[8];
            #pragma unroll
            for (int k = 0; k < 8; k++)
                av[k] = __ldcs(&adj[(row0 + rowb + rr8 + k) * NN + myj]);
            #pragma unroll
            for (int k = 0; k < 8; k++) {
                const float e = h1s[rowb + rr8 + k] + h2v;
                const float s = fmaxf(e, ALPHA * e);      // LeakyReLU
                const float p = (av[k] > 0) ? __expf(s) : 0.f;
                ps[rowb + rr8 + k][lane] = p;             // banks (row+lane)%32: clean
            }
        }
        __syncthreads();

        // ---- PV: acc[8x8] += p[r] * h[j][c]  via packed fma.rn.f32x2 ----
        #pragma unroll 2
        for (int j = 0; j < BJ; j++) {
            const ulonglong2* hp = (const ulonglong2*)&hts[j * DD + c0];
            const ulonglong2 ha = hp[0], hb = hp[1];      // 8 cols, 2x LDS.128
            #pragma unroll
            for (int rr = 0; rr < 8; rr++) {
                const float p = ps[r0 + rr][j];
                unsigned long long pp;
                asm("mov.b64 %0,{%1,%1};" : "=l"(pp) : "f"(p));
                asm("fma.rn.f32x2 %0,%1,%2,%0;" : "+l"(acc[rr*4+0]) : "l"(pp), "l"(ha.x));
                asm("fma.rn.f32x2 %0,%1,%2,%0;" : "+l"(acc[rr*4+1]) : "l"(pp), "l"(ha.y));
                asm("fma.rn.f32x2 %0,%1,%2,%0;" : "+l"(acc[rr*4+2]) : "l"(pp), "l"(hb.x));
                asm("fma.rn.f32x2 %0,%1,%2,%0;" : "+l"(acc[rr*4+3]) : "l"(pp), "l"(hb.y));
            }
        }

        // ---- Z partial: thread tid owns row tid ----
        {
            float zs = 0.f;
            #pragma unroll 8
            for (int j = 0; j < BJ; j++) zs += ps[tid][j];
            zacc += zs;
        }
        __syncthreads();
    }

    // epilogue: partial numerator + partial Z to scratch
    #pragma unroll
    for (int rr = 0; rr < 8; rr++) {
        ulonglong2* dst = (ulonglong2*)&g_acc[((size_t)js * NN + row0 + r0 + rr) * DD + c0];
        ulonglong2 v0, v1;
        v0.x = acc[rr*4+0]; v0.y = acc[rr*4+1];
        v1.x = acc[rr*4+2]; v1.y = acc[rr*4+3];
        dst[0] = v0; dst[1] = v1;
    }
    g_Z[js * NN + row0 + tid] = zacc;
}

// ---------------- kernel 4: combine splits, normalize, ELU ----------------
__global__ void __launch_bounds__(256) combine_kernel(float* __restrict__ out) {
    const int gid = blockIdx.x * 256 + threadIdx.x;
    const int i = gid >> 6;
    float s = 0.f, z = 0.f;
    #pragma unroll
    for (int q = 0; q < JS; q++) {
        s += g_acc[(size_t)q * NN * DD + gid];
        z += g_Z[q * NN + i];
    }
    const float o = s / z;
    out[gid] = (o > 0.f) ? o : expm1f(o);   // ELU (alpha=1)
}

// ---------------- launcher ----------------
extern "C" void kernel_launch(void* const* d_in, const int* in_sizes, int n_in,
                              void* d_out, int out_size) {
    const float* features = (const float*)d_in[0];   // [8192,512]
    const int*   adj      = (const int*)d_in[1];     // [8192,8192]
    const float* W        = (const float*)d_in[2];   // [512,64]
    const float* a        = (const float*)d_in[3];   // [128,1]
    float* out = (float*)d_out;                      // [8192,64]

    gemm_h_kernel<<<NN/16, 256>>>(features, W);
    proj_kernel<<<NN/8, 256>>>(a);
    attn_kernel<<<dim3(JS, NN/BI), 256>>>(adj);
    combine_kernel<<<(NN*DD)/256, 256>>>(out);
}

// round 3
// speedup vs baseline: 2.7952x; 2.7952x over previous
#include <cuda_runtime.h>
#include <cuda_bf16.h>
#include <cstdint>

#define NN 8192
#define IND 512
#define DD 64
#define ALPHA 0.2f

#define JS 2
#define JLEN (NN/JS)      // 4096
#define KT 64             // j per tile
#define NTILES (JLEN/KT)  // 64

// -------- device scratch --------
__device__ __align__(16) float g_h[NN*DD];
__device__ __align__(16) float g_h1[NN];
__device__ __align__(16) float g_h2[NN];
__device__ __align__(16) __nv_bfloat16 g_ht_hi[(size_t)DD*NN];
__device__ __align__(16) __nv_bfloat16 g_ht_lo[(size_t)DD*NN];
__device__ __align__(16) float g_acc[(size_t)JS*NN*DD];
__device__ __align__(16) float g_Z[JS*NN];

// ---------------- kernel 1: h = X @ W ----------------
__global__ void __launch_bounds__(256) gemm_h_kernel(const float* __restrict__ X,
                                                     const float* __restrict__ W) {
    __shared__ float xs[16][IND];
    const int tid = threadIdx.x;
    const int row0 = blockIdx.x * 16;
    {
        const float4* src = (const float4*)(X + (size_t)row0 * IND);
        float4* dst = (float4*)&xs[0][0];
        #pragma unroll
        for (int i = 0; i < 8; i++) dst[tid + i*256] = src[tid + i*256];
    }
    __syncthreads();
    const int c  = tid & 63;
    const int rg = tid >> 6;
    float a0 = 0.f, a1 = 0.f, a2 = 0.f, a3 = 0.f;
    #pragma unroll 4
    for (int k = 0; k < IND; k++) {
        const float w = W[k*DD + c];
        a0 += xs[rg*4+0][k] * w;
        a1 += xs[rg*4+1][k] * w;
        a2 += xs[rg*4+2][k] * w;
        a3 += xs[rg*4+3][k] * w;
    }
    g_h[(row0 + rg*4+0)*DD + c] = a0;
    g_h[(row0 + rg*4+1)*DD + c] = a1;
    g_h[(row0 + rg*4+2)*DD + c] = a2;
    g_h[(row0 + rg*4+3)*DD + c] = a3;
}

// ---------------- kernel 2: transpose h -> ht_hi/ht_lo (bf16 split) ----------------
__global__ void __launch_bounds__(256) ht_kernel() {
    __shared__ float ts[64][65];
    const int tid = threadIdx.x;
    const int j0 = blockIdx.x * 64;
    #pragma unroll
    for (int k = 0; k < 16; ++k) {
        int e = k*256 + tid;
        ts[e>>6][e&63] = g_h[(j0 + (e>>6))*DD + (e&63)];
    }
    __syncthreads();
    #pragma unroll
    for (int k = 0; k < 16; ++k) {
        int e = k*256 + tid;
        int c = e >> 6, jj = e & 63;
        float v = ts[jj][c];
        __nv_bfloat16 hb = __float2bfloat16(v);
        g_ht_hi[(size_t)c*NN + j0 + jj] = hb;
        g_ht_lo[(size_t)c*NN + j0 + jj] = __float2bfloat16(v - __bfloat162float(hb));
    }
}

// ---------------- kernel 3: h1 / h2 projections ----------------
__global__ void __launch_bounds__(256) proj_kernel(const float* __restrict__ a) {
    const int w = threadIdx.x >> 5, lane = threadIdx.x & 31;
    const int row = blockIdx.x * 8 + w;
    const float x0 = g_h[row*DD + lane];
    const float x1 = g_h[row*DD + 32 + lane];
    float s1 = x0 * a[lane]      + x1 * a[lane + 32];
    float s2 = x0 * a[64 + lane] + x1 * a[96 + lane];
    #pragma unroll
    for (int o = 16; o > 0; o >>= 1) {
        s1 += __shfl_xor_sync(0xffffffffu, s1, o);
        s2 += __shfl_xor_sync(0xffffffffu, s2, o);
    }
    if (lane == 0) { g_h1[row] = s1; g_h2[row] = s2; }
}

// ---------------- kernel 4: fused attention, mma.sync PV ----------------
__device__ __forceinline__ float pexp(int a, float e) {
    const float s = fmaxf(e, ALPHA * e);
    const float p = __expf(s);
    return (a > 0) ? p : 0.f;
}
// pack (x,y) -> bf16x2 hi, residual -> lo.  low half = x (element j), high = y (j+1)
__device__ __forceinline__ uint32_t pack_hilo(float x, float y, uint32_t& lo) {
    __nv_bfloat162 H = __float22bfloat162_rn(make_float2(x, y));
    float2 f = __bfloat1622float2(H);
    __nv_bfloat162 L = __float22bfloat162_rn(make_float2(x - f.x, y - f.y));
    lo = *reinterpret_cast<uint32_t*>(&L);
    return *reinterpret_cast<uint32_t*>(&H);
}
#define MMA(d, a, b0, b1) \
    asm volatile("mma.sync.aligned.m16n8k16.row.col.f32.bf16.bf16.f32 " \
        "{%0,%1,%2,%3},{%4,%5,%6,%7},{%8,%9},{%0,%1,%2,%3};" \
        : "+f"((d)[0]), "+f"((d)[1]), "+f"((d)[2]), "+f"((d)[3]) \
        : "r"((a)[0]), "r"((a)[1]), "r"((a)[2]), "r"((a)[3]), "r"(b0), "r"(b1))

__global__ void __launch_bounds__(256, 1) attn_kernel(const int* __restrict__ adj) {
    // [buf][hi/lo][c][j] ; stride 72 -> B-frag LDS conflict-free
    __shared__ __nv_bfloat16 hts[2][2][64][72];   // 36 KB

    const int tid = threadIdx.x, lane = tid & 31, w = tid >> 5;
    const int jsb = blockIdx.x;
    const int row0 = blockIdx.y * 128;
    const int jbase = jsb * JLEN;
    const int g  = row0 + w * 16 + (lane >> 2);   // A-frag row (and g+8)
    const int jq = (lane & 3) * 2;                // A-frag k offset

    const float h1a = g_h1[g];
    const float h1b = g_h1[g + 8];
    const int* adjA = adj + (size_t)g * NN;
    const int* adjB = adj + (size_t)(g + 8) * NN;

    float acc[8][4];
    #pragma unroll
    for (int nb = 0; nb < 8; nb++) { acc[nb][0]=acc[nb][1]=acc[nb][2]=acc[nb][3]=0.f; }
    float z0 = 0.f, z1 = 0.f;

    // stage tile 0
    #pragma unroll
    for (int q = 0; q < 4; q++) {
        const int cidx = tid + q * 256;
        const int c = cidx >> 4, jg = (cidx & 15) * 4;
        *(uint2*)&hts[0][0][c][jg] = *(const uint2*)(g_ht_hi + (size_t)c*NN + jbase + jg);
        *(uint2*)&hts[0][1][c][jg] = *(const uint2*)(g_ht_lo + (size_t)c*NN + jbase + jg);
    }
    __syncthreads();

    for (int t = 0; t < NTILES; t++) {
        const int j0 = jbase + t * KT;
        const int cur = t & 1;

        // prefetch next H tile into registers (hidden under P-gen + MMA)
        uint2 pf_h[4], pf_l[4];
        if (t < NTILES - 1) {
            const int jn = j0 + KT;
            #pragma unroll
            for (int q = 0; q < 4; q++) {
                const int cidx = tid + q * 256;
                const int c = cidx >> 4, jg = (cidx & 15) * 4;
                pf_h[q] = *(const uint2*)(g_ht_hi + (size_t)c*NN + jn + jg);
                pf_l[q] = *(const uint2*)(g_ht_lo + (size_t)c*NN + jn + jg);
            }
        }

        // ---- build A fragments (P values) directly in mma layout ----
        uint32_t ahi[4][4], alo[4][4];
        #pragma unroll
        for (int kb = 0; kb < 4; kb++) {
            const int jb = j0 + kb * 16 + jq;
            const int2 A0 = __ldcs((const int2*)(adjA + jb));
            const int2 A1 = __ldcs((const int2*)(adjB + jb));
            const int2 A2 = __ldcs((const int2*)(adjA + jb + 8));
            const int2 A3 = __ldcs((const int2*)(adjB + jb + 8));
            const float2 H0 = *(const float2*)(g_h2 + jb);
            const float2 H1 = *(const float2*)(g_h2 + jb + 8);
            const float p00 = pexp(A0.x, h1a + H0.x), p01 = pexp(A0.y, h1a + H0.y);
            const float p10 = pexp(A1.x, h1b + H0.x), p11 = pexp(A1.y, h1b + H0.y);
            const float p02 = pexp(A2.x, h1a + H1.x), p03 = pexp(A2.y, h1a + H1.y);
            const float p12 = pexp(A3.x, h1b + H1.x), p13 = pexp(A3.y, h1b + H1.y);
            z0 += (p00 + p01) + (p02 + p03);
            z1 += (p10 + p11) + (p12 + p13);
            ahi[kb][0] = pack_hilo(p00, p01, alo[kb][0]);
            ahi[kb][1] = pack_hilo(p10, p11, alo[kb][1]);
            ahi[kb][2] = pack_hilo(p02, p03, alo[kb][2]);
            ahi[kb][3] = pack_hilo(p12, p13, alo[kb][3]);
        }

        // ---- MMAs: acc += P_hi*H_hi + P_lo*H_hi + P_hi*H_lo ----
        const int brow = lane >> 2;
        #pragma unroll
        for (int nb = 0; nb < 8; nb++) {
            const int c = nb * 8 + brow;
            #pragma unroll
            for (int kb = 0; kb < 4; kb++) {
                const uint32_t bh0 = *(const uint32_t*)&hts[cur][0][c][kb*16 + jq];
                const uint32_t bh1 = *(const uint32_t*)&hts[cur][0][c][kb*16 + jq + 8];
                const uint32_t bl0 = *(const uint32_t*)&hts[cur][1][c][kb*16 + jq];
                const uint32_t bl1 = *(const uint32_t*)&hts[cur][1][c][kb*16 + jq + 8];
                MMA(acc[nb], ahi[kb], bh0, bh1);
                MMA(acc[nb], alo[kb], bh0, bh1);
                MMA(acc[nb], ahi[kb], bl0, bl1);
            }
        }

        // commit prefetched tile to the other buffer
        if (t < NTILES - 1) {
            #pragma unroll
            for (int q = 0; q < 4; q++) {
                const int cidx = tid + q * 256;
                const int c = cidx >> 4, jg = (cidx & 15) * 4;
                *(uint2*)&hts[cur ^ 1][0][c][jg] = pf_h[q];
                *(uint2*)&hts[cur ^ 1][1][c][jg] = pf_l[q];
            }
        }
        __syncthreads();
    }

    // ---- Z: reduce across the 4 lanes sharing a row ----
    z0 += __shfl_xor_sync(0xffffffffu, z0, 1);
    z0 += __shfl_xor_sync(0xffffffffu, z0, 2);
    z1 += __shfl_xor_sync(0xffffffffu, z1, 1);
    z1 += __shfl_xor_sync(0xffffffffu, z1, 2);
    if ((lane & 3) == 0) {
        g_Z[jsb*NN + g]     = z0;
        g_Z[jsb*NN + g + 8] = z1;
    }

    // ---- store partial numerators ----
    #pragma unroll
    for (int nb = 0; nb < 8; nb++) {
        float2 v0; v0.x = acc[nb][0]; v0.y = acc[nb][1];
        float2 v1; v1.x = acc[nb][2]; v1.y = acc[nb][3];
        *(float2*)&g_acc[((size_t)jsb*NN + g    )*DD + nb*8 + jq] = v0;
        *(float2*)&g_acc[((size_t)jsb*NN + g + 8)*DD + nb*8 + jq] = v1;
    }
}

// ---------------- kernel 5: combine splits, normalize, ELU ----------------
__global__ void __launch_bounds__(256) combine_kernel(float* __restrict__ out) {
    const int gid = blockIdx.x * 256 + threadIdx.x;
    const int i = gid >> 6;
    const float s = g_acc[gid] + g_acc[(size_t)NN*DD + gid];
    const float z = g_Z[i] + g_Z[NN + i];
    const float o = s / z;
    out[gid] = (o > 0.f) ? o : expm1f(o);
}

// ---------------- launcher ----------------
extern "C" void kernel_launch(void* const* d_in, const int* in_sizes, int n_in,
                              void* d_out, int out_size) {
    const float* features = (const float*)d_in[0];
    const int*   adj      = (const int*)d_in[1];
    const float* W        = (const float*)d_in[2];
    const float* a        = (const float*)d_in[3];
    float* out = (float*)d_out;

    gemm_h_kernel<<<NN/16, 256>>>(features, W);
    ht_kernel<<<NN/64, 256>>>();
    proj_kernel<<<NN/8, 256>>>(a);
    attn_kernel<<<dim3(JS, NN/128), 256>>>(adj);
    combine_kernel<<<(NN*DD)/256, 256>>>(out);
}

// round 4
// speedup vs baseline: 3.2371x; 1.1581x over previous
#include <cuda_runtime.h>
#include <cuda_bf16.h>
#include <cstdint>

#define NN 8192
#define IND 512
#define DD 64
#define ALPHA 0.2f

#define JS 2
#define JLEN (NN/JS)      // 4096
#define KT 64             // j per tile
#define NTILES (JLEN/KT)  // 64

// -------- device scratch --------
__device__ __align__(16) float g_h[NN*DD];
__device__ __align__(16) float g_h1[NN];
__device__ __align__(16) float g_h2[NN];
__device__ __align__(16) __nv_bfloat16 g_ht_hi[(size_t)DD*NN];
__device__ __align__(16) __nv_bfloat16 g_ht_lo[(size_t)DD*NN];
__device__ __align__(16) float g_acc[(size_t)JS*NN*DD];
__device__ __align__(16) float g_Z[JS*NN];

// -------- helpers --------
__device__ __forceinline__ uint32_t s2u(const void* p) {
    uint32_t a;
    asm("{ .reg .u64 t; cvta.to.shared.u64 t, %1; cvt.u32.u64 %0, t; }" : "=r"(a) : "l"(p));
    return a;
}
#define CPA16(dst, src) asm volatile("cp.async.cg.shared.global [%0], [%1], 16;" :: "r"(dst), "l"(src))
#define CPCOMMIT()      asm volatile("cp.async.commit_group;" ::: "memory")
#define CPWAIT1()       asm volatile("cp.async.wait_group 1;" ::: "memory")
#define LDM4(r, a) \
    asm volatile("ldmatrix.sync.aligned.m8n8.x4.shared.b16 {%0,%1,%2,%3},[%4];" \
        : "=r"((r)[0]), "=r"((r)[1]), "=r"((r)[2]), "=r"((r)[3]) : "r"(a))
#define MMA(d, a, b0, b1) \
    asm volatile("mma.sync.aligned.m16n8k16.row.col.f32.bf16.bf16.f32 " \
        "{%0,%1,%2,%3},{%4,%5,%6,%7},{%8,%9},{%0,%1,%2,%3};" \
        : "+f"((d)[0]), "+f"((d)[1]), "+f"((d)[2]), "+f"((d)[3]) \
        : "r"((a)[0]), "r"((a)[1]), "r"((a)[2]), "r"((a)[3]), "r"(b0), "r"(b1))

// ---------------- kernel 1: h = X @ W ----------------
__global__ void __launch_bounds__(256) gemm_h_kernel(const float* __restrict__ X,
                                                     const float* __restrict__ W) {
    __shared__ float xs[16][IND];
    const int tid = threadIdx.x;
    const int row0 = blockIdx.x * 16;
    {
        const float4* src = (const float4*)(X + (size_t)row0 * IND);
        float4* dst = (float4*)&xs[0][0];
        #pragma unroll
        for (int i = 0; i < 8; i++) dst[tid + i*256] = src[tid + i*256];
    }
    __syncthreads();
    const int c  = tid & 63;
    const int rg = tid >> 6;
    float a0 = 0.f, a1 = 0.f, a2 = 0.f, a3 = 0.f;
    #pragma unroll 4
    for (int k = 0; k < IND; k++) {
        const float w = W[k*DD + c];
        a0 += xs[rg*4+0][k] * w;
        a1 += xs[rg*4+1][k] * w;
        a2 += xs[rg*4+2][k] * w;
        a3 += xs[rg*4+3][k] * w;
    }
    g_h[(row0 + rg*4+0)*DD + c] = a0;
    g_h[(row0 + rg*4+1)*DD + c] = a1;
    g_h[(row0 + rg*4+2)*DD + c] = a2;
    g_h[(row0 + rg*4+3)*DD + c] = a3;
}

// ---------------- kernel 2: transpose h -> ht_hi/ht_lo (bf16 split) ----------------
__global__ void __launch_bounds__(256) ht_kernel() {
    __shared__ float ts[64][65];
    const int tid = threadIdx.x;
    const int j0 = blockIdx.x * 64;
    #pragma unroll
    for (int k = 0; k < 16; ++k) {
        int e = k*256 + tid;
        ts[e>>6][e&63] = g_h[(j0 + (e>>6))*DD + (e&63)];
    }
    __syncthreads();
    #pragma unroll
    for (int k = 0; k < 16; ++k) {
        int e = k*256 + tid;
        int c = e >> 6, jj = e & 63;
        float v = ts[jj][c];
        __nv_bfloat16 hb = __float2bfloat16(v);
        g_ht_hi[(size_t)c*NN + j0 + jj] = hb;
        g_ht_lo[(size_t)c*NN + j0 + jj] = __float2bfloat16(v - __bfloat162float(hb));
    }
}

// ---------------- kernel 3: h1 / h2 projections ----------------
__global__ void __launch_bounds__(256) proj_kernel(const float* __restrict__ a) {
    const int w = threadIdx.x >> 5, lane = threadIdx.x & 31;
    const int row = blockIdx.x * 8 + w;
    const float x0 = g_h[row*DD + lane];
    const float x1 = g_h[row*DD + 32 + lane];
    float s1 = x0 * a[lane]      + x1 * a[lane + 32];
    float s2 = x0 * a[64 + lane] + x1 * a[96 + lane];
    #pragma unroll
    for (int o = 16; o > 0; o >>= 1) {
        s1 += __shfl_xor_sync(0xffffffffu, s1, o);
        s2 += __shfl_xor_sync(0xffffffffu, s2, o);
    }
    if (lane == 0) { g_h1[row] = s1; g_h2[row] = s2; }
}

// ---------------- kernel 4: fused attention ----------------
__device__ __forceinline__ float pexp(int a, float e) {
    const float s = fmaxf(e, ALPHA * e);
    const float p = __expf(s);
    return (a > 0) ? p : 0.f;
}
__device__ __forceinline__ uint32_t pack_hilo(float x, float y, uint32_t& lo) {
    __nv_bfloat162 H = __float22bfloat162_rn(make_float2(x, y));
    float2 f = __bfloat1622float2(H);
    __nv_bfloat162 L = __float22bfloat162_rn(make_float2(x - f.x, y - f.y));
    lo = *reinterpret_cast<uint32_t*>(&L);
    return *reinterpret_cast<uint32_t*>(&H);
}

// 128 threads (4 warps), 64 rows per CTA. grid (JS, NN/64).
__global__ void __launch_bounds__(128, 3) attn_kernel(const int* __restrict__ adj) {
    // [buf][hi/lo][c][j]; stride 72 -> conflict-free ldmatrix & cp.async rows
    __shared__ __nv_bfloat16 hts[2][2][64][72];   // 36 KB

    const int tid = threadIdx.x, lane = tid & 31, w = tid >> 5;
    const int jsb = blockIdx.x;
    const int row0 = blockIdx.y * 64;
    const int jbase = jsb * JLEN;
    const int g  = row0 + w * 16 + (lane >> 2);   // A-frag rows g, g+8
    const int jq = (lane & 3) * 2;

    const float h1a = g_h1[g];
    const float h1b = g_h1[g + 8];
    const int* adjA = adj + (size_t)g * NN;
    const int* adjB = adj + (size_t)(g + 8) * NN;

    // ldmatrix per-lane address pieces: row within 8-block, matrix quad
    const int lmr = lane & 7;            // matrix row (n)
    const int lmq = (lane >> 3) * 8;     // k-offset selecting which 8x8 matrix
    const uint32_t smem0 = s2u(&hts[0][0][0][0]);
    const uint32_t PL = 64 * 72 * 2;                 // lo-plane offset (bytes)
    const uint32_t BUFB = 2 * PL;                    // buffer stride (bytes)

    // staging: 8x cp.async of 16B per thread per tile (hi+lo)
    uint32_t cdst[4];
    const __nv_bfloat16* csrc_h[4];
    const __nv_bfloat16* csrc_l[4];
    #pragma unroll
    for (int q = 0; q < 4; q++) {
        const int idx = tid + q * 128;        // 0..511
        const int c = idx >> 3, seg = idx & 7;
        cdst[q] = smem0 + (uint32_t)(c * 72 + seg * 8) * 2;
        csrc_h[q] = g_ht_hi + (size_t)c * NN + seg * 8;
        csrc_l[q] = g_ht_lo + (size_t)c * NN + seg * 8;
    }

    float acc[8][4];
    #pragma unroll
    for (int nb = 0; nb < 8; nb++) { acc[nb][0]=acc[nb][1]=acc[nb][2]=acc[nb][3]=0.f; }
    float z0 = 0.f, z1 = 0.f;

    // prologue: stage tile 0 into buf 0
    #pragma unroll
    for (int q = 0; q < 4; q++) {
        CPA16(cdst[q],      csrc_h[q] + jbase);
        CPA16(cdst[q] + PL, csrc_l[q] + jbase);
    }
    CPCOMMIT();

    for (int t = 0; t < NTILES; t++) {
        const int j0 = jbase + t * KT;
        const uint32_t curb = smem0 + (uint32_t)(t & 1) * BUFB;

        // stage next tile into other buffer
        if (t + 1 < NTILES) {
            const uint32_t nxtb = (uint32_t)((t + 1) & 1) * BUFB;
            #pragma unroll
            for (int q = 0; q < 4; q++) {
                CPA16(cdst[q] + nxtb,      csrc_h[q] + j0 + KT);
                CPA16(cdst[q] + nxtb + PL, csrc_l[q] + j0 + KT);
            }
        }
        CPCOMMIT();

        // ---- A fragments (P values) in mma layout; overlaps cp.async ----
        uint32_t ahi[4][4], alo[4][4];
        #pragma unroll
        for (int kb = 0; kb < 4; kb++) {
            const int jb = j0 + kb * 16 + jq;
            const int2 A0 = __ldcs((const int2*)(adjA + jb));
            const int2 A1 = __ldcs((const int2*)(adjB + jb));
            const int2 A2 = __ldcs((const int2*)(adjA + jb + 8));
            const int2 A3 = __ldcs((const int2*)(adjB + jb + 8));
            const float2 H0 = *(const float2*)(g_h2 + jb);
            const float2 H1 = *(const float2*)(g_h2 + jb + 8);
            const float p00 = pexp(A0.x, h1a + H0.x), p01 = pexp(A0.y, h1a + H0.y);
            const float p10 = pexp(A1.x, h1b + H0.x), p11 = pexp(A1.y, h1b + H0.y);
            const float p02 = pexp(A2.x, h1a + H1.x), p03 = pexp(A2.y, h1a + H1.y);
            const float p12 = pexp(A3.x, h1b + H1.x), p13 = pexp(A3.y, h1b + H1.y);
            z0 += (p00 + p01) + (p02 + p03);
            z1 += (p10 + p11) + (p12 + p13);
            ahi[kb][0] = pack_hilo(p00, p01, alo[kb][0]);
            ahi[kb][1] = pack_hilo(p10, p11, alo[kb][1]);
            ahi[kb][2] = pack_hilo(p02, p03, alo[kb][2]);
            ahi[kb][3] = pack_hilo(p12, p13, alo[kb][3]);
        }

        CPWAIT1();
        __syncthreads();

        // ---- MMAs with ldmatrix B loads ----
        #pragma unroll
        for (int nb = 0; nb < 8; nb++) {
            const uint32_t rowa = curb + (uint32_t)((nb * 8 + lmr) * 72 + lmq) * 2;
            uint32_t bh[8], bl[8];
            LDM4(bh,     rowa);          // k 0..31  -> kb0,kb1
            LDM4(bh + 4, rowa + 64);     // k 32..63 -> kb2,kb3
            LDM4(bl,     rowa + PL);
            LDM4(bl + 4, rowa + PL + 64);
            #pragma unroll
            for (int kb = 0; kb < 4; kb++) {
                MMA(acc[nb], ahi[kb], bh[2*kb], bh[2*kb+1]);
                MMA(acc[nb], alo[kb], bh[2*kb], bh[2*kb+1]);
                MMA(acc[nb], ahi[kb], bl[2*kb], bl[2*kb+1]);
            }
        }
        __syncthreads();
    }

    // ---- Z reduce across 4 lanes sharing a row ----
    z0 += __shfl_xor_sync(0xffffffffu, z0, 1);
    z0 += __shfl_xor_sync(0xffffffffu, z0, 2);
    z1 += __shfl_xor_sync(0xffffffffu, z1, 1);
    z1 += __shfl_xor_sync(0xffffffffu, z1, 2);
    if ((lane & 3) == 0) {
        g_Z[jsb*NN + g]     = z0;
        g_Z[jsb*NN + g + 8] = z1;
    }

    // ---- partial numerators ----
    #pragma unroll
    for (int nb = 0; nb < 8; nb++) {
        float2 v0; v0.x = acc[nb][0]; v0.y = acc[nb][1];
        float2 v1; v1.x = acc[nb][2]; v1.y = acc[nb][3];
        *(float2*)&g_acc[((size_t)jsb*NN + g    )*DD + nb*8 + jq] = v0;
        *(float2*)&g_acc[((size_t)jsb*NN + g + 8)*DD + nb*8 + jq] = v1;
    }
}

// ---------------- kernel 5: combine splits, normalize, ELU ----------------
__global__ void __launch_bounds__(256) combine_kernel(float* __restrict__ out) {
    const int gid = blockIdx.x * 256 + threadIdx.x;
    const int i = gid >> 6;
    const float s = g_acc[gid] + g_acc[(size_t)NN*DD + gid];
    const float z = g_Z[i] + g_Z[NN + i];
    const float o = s / z;
    out[gid] = (o > 0.f) ? o : expm1f(o);
}

// ---------------- launcher ----------------
extern "C" void kernel_launch(void* const* d_in, const int* in_sizes, int n_in,
                              void* d_out, int out_size) {
    const float* features = (const float*)d_in[0];
    const int*   adj      = (const int*)d_in[1];
    const float* W        = (const float*)d_in[2];
    const float* a        = (const float*)d_in[3];
    float* out = (float*)d_out;

    gemm_h_kernel<<<NN/16, 256>>>(features, W);
    ht_kernel<<<NN/64, 256>>>();
    proj_kernel<<<NN/8, 256>>>(a);
    attn_kernel<<<dim3(JS, NN/64), 128>>>(adj);
    combine_kernel<<<(NN*DD)/256, 256>>>(out);
}

// round 5
// speedup vs baseline: 3.2377x; 1.0002x over previous
#include <cuda_runtime.h>
#include <cuda_bf16.h>
#include <cstdint>

#define NN 8192
#define IND 512
#define DD 64
#define ALPHA 0.2f

#define JS 4
#define JLEN (NN/JS)      // 2048
#define KT 64             // j per tile
#define NTILES (JLEN/KT)  // 32

// -------- device scratch --------
__device__ __align__(16) float g_h1[NN];
__device__ __align__(16) float g_h2[NN];
__device__ __align__(16) __nv_bfloat16 g_ht_hi[(size_t)DD*NN];
__device__ __align__(16) __nv_bfloat16 g_ht_lo[(size_t)DD*NN];
__device__ __align__(16) float g_acc[(size_t)JS*NN*DD];
__device__ __align__(16) float g_Z[JS*NN];

// -------- helpers --------
__device__ __forceinline__ uint32_t s2u(const void* p) {
    uint32_t a;
    asm("{ .reg .u64 t; cvta.to.shared.u64 t, %1; cvt.u32.u64 %0, t; }" : "=r"(a) : "l"(p));
    return a;
}
#define CPA16(dst, src) asm volatile("cp.async.cg.shared.global [%0], [%1], 16;" :: "r"(dst), "l"(src))
#define CPCOMMIT()      asm volatile("cp.async.commit_group;" ::: "memory")
#define CPWAIT1()       asm volatile("cp.async.wait_group 1;" ::: "memory")
#define LDM4(r, a) \
    asm volatile("ldmatrix.sync.aligned.m8n8.x4.shared.b16 {%0,%1,%2,%3},[%4];" \
        : "=r"((r)[0]), "=r"((r)[1]), "=r"((r)[2]), "=r"((r)[3]) : "r"(a))
#define MMA(d, a, b0, b1) \
    asm volatile("mma.sync.aligned.m16n8k16.row.col.f32.bf16.bf16.f32 " \
        "{%0,%1,%2,%3},{%4,%5,%6,%7},{%8,%9},{%0,%1,%2,%3};" \
        : "+f"((d)[0]), "+f"((d)[1]), "+f"((d)[2]), "+f"((d)[3]) \
        : "r"((a)[0]), "r"((a)[1]), "r"((a)[2]), "r"((a)[3]), "r"(b0), "r"(b1))

// ---------------- kernel 1: fused  h=X@W  ->  ht_hi/lo (transposed bf16 split), h1, h2 ----
__global__ void __launch_bounds__(256) gemm_fused_kernel(const float* __restrict__ X,
                                                         const float* __restrict__ W,
                                                         const float* __restrict__ av) {
    __shared__ float xs[16][IND];        // 32 KB
    __shared__ float r1[16][64];         // proj partials
    __shared__ float r2[16][64];
    const int tid = threadIdx.x;
    const int row0 = blockIdx.x * 16;
    {
        const float4* src = (const float4*)(X + (size_t)row0 * IND);
        float4* dst = (float4*)&xs[0][0];
        #pragma unroll
        for (int i = 0; i < 8; i++) dst[tid + i*256] = src[tid + i*256];
    }
    __syncthreads();
    const int c  = tid & 63;
    const int rg = tid >> 6;
    float a0 = 0.f, a1 = 0.f, a2 = 0.f, a3 = 0.f;
    #pragma unroll 4
    for (int k = 0; k < IND; k++) {
        const float w = W[k*DD + c];
        a0 += xs[rg*4+0][k] * w;
        a1 += xs[rg*4+1][k] * w;
        a2 += xs[rg*4+2][k] * w;
        a3 += xs[rg*4+3][k] * w;
    }
    // transposed bf16 hi/lo planes: 4 consecutive rows -> one 8B store per plane
    {
        float v[4] = {a0, a1, a2, a3};
        __nv_bfloat16 hb[4], lb[4];
        #pragma unroll
        for (int i = 0; i < 4; i++) {
            hb[i] = __float2bfloat16(v[i]);
            lb[i] = __float2bfloat16(v[i] - __bfloat162float(hb[i]));
        }
        *(uint2*)(g_ht_hi + (size_t)c*NN + row0 + rg*4) = *(uint2*)hb;
        *(uint2*)(g_ht_lo + (size_t)c*NN + row0 + rg*4) = *(uint2*)lb;
    }
    // proj partials
    const float w1 = av[c], w2 = av[64 + c];
    r1[rg*4+0][c] = a0 * w1;  r2[rg*4+0][c] = a0 * w2;
    r1[rg*4+1][c] = a1 * w1;  r2[rg*4+1][c] = a1 * w2;
    r1[rg*4+2][c] = a2 * w1;  r2[rg*4+2][c] = a2 * w2;
    r1[rg*4+3][c] = a3 * w1;  r2[rg*4+3][c] = a3 * w2;
    __syncthreads();
    const int wid = tid >> 5, lane = tid & 31;
    #pragma unroll
    for (int rr = 0; rr < 2; rr++) {
        const int row = wid * 2 + rr;
        float s1 = r1[row][lane] + r1[row][lane + 32];
        float s2 = r2[row][lane] + r2[row][lane + 32];
        #pragma unroll
        for (int o = 16; o > 0; o >>= 1) {
            s1 += __shfl_xor_sync(0xffffffffu, s1, o);
            s2 += __shfl_xor_sync(0xffffffffu, s2, o);
        }
        if (lane == 0) { g_h1[row0 + row] = s1; g_h2[row0 + row] = s2; }
    }
}

// ---------------- kernel 2: fused attention ----------------
__device__ __forceinline__ float pexp(int a, float e) {
    const float s = fmaxf(e, ALPHA * e);
    const float p = __expf(s);
    return (a > 0) ? p : 0.f;
}
__device__ __forceinline__ uint32_t pack_hilo(float x, float y, uint32_t& lo) {
    __nv_bfloat162 H = __float22bfloat162_rn(make_float2(x, y));
    float2 f = __bfloat1622float2(H);
    __nv_bfloat162 L = __float22bfloat162_rn(make_float2(x - f.x, y - f.y));
    lo = *reinterpret_cast<uint32_t*>(&L);
    return *reinterpret_cast<uint32_t*>(&H);
}

// 128 threads (4 warps), 64 rows per CTA. grid (JS, NN/64).
__global__ void __launch_bounds__(128, 2) attn_kernel(const int* __restrict__ adj) {
    // [buf][hi/lo][c][j], 128B rows, XOR(seg^row) swizzle -> conflict-free
    __shared__ __nv_bfloat16 hts[2][2][64][64];   // 32 KB

    const int tid = threadIdx.x, lane = tid & 31, w = tid >> 5;
    const int jsb = blockIdx.x;
    const int row0 = blockIdx.y * 64;
    const int jbase = jsb * JLEN;
    const int g  = row0 + w * 16 + (lane >> 2);   // A-frag rows g, g+8
    const int jq = (lane & 3) * 2;

    const float h1a = g_h1[g];
    const float h1b = g_h1[g + 8];
    const int* adjA = adj + (size_t)g * NN;
    const int* adjB = adj + (size_t)(g + 8) * NN;

    const int lmr = lane & 7;
    const uint32_t smem0 = s2u(&hts[0][0][0][0]);
    const uint32_t PL   = 64 * 64 * 2;            // plane stride (bytes)
    const uint32_t BUFB = 2 * PL;

    // cp.async chunk mapping (c, seg), seg XOR-swizzled by row
    uint32_t cdst[4];
    const __nv_bfloat16* csrc_h[4];
    const __nv_bfloat16* csrc_l[4];
    #pragma unroll
    for (int q = 0; q < 4; q++) {
        const int idx = tid + q * 128;            // 0..511
        const int c = idx >> 3, seg = idx & 7;
        const int phys = seg ^ (c & 7);
        cdst[q] = smem0 + (uint32_t)(c * 64 + phys * 8) * 2;
        csrc_h[q] = g_ht_hi + (size_t)c * NN + seg * 8;
        csrc_l[q] = g_ht_lo + (size_t)c * NN + seg * 8;
    }

    float acc[8][4];
    #pragma unroll
    for (int nb = 0; nb < 8; nb++) { acc[nb][0]=acc[nb][1]=acc[nb][2]=acc[nb][3]=0.f; }
    float z0 = 0.f, z1 = 0.f;

    // ---- prologue: prefetch adj/h2 for tile 0, stage H tile 0 ----
    int2 pa[4][4];
    float2 ph0[4], ph1[4];
    #pragma unroll
    for (int kb = 0; kb < 4; kb++) {
        const int jb = jbase + kb * 16 + jq;
        pa[kb][0] = __ldcs((const int2*)(adjA + jb));
        pa[kb][1] = __ldcs((const int2*)(adjB + jb));
        pa[kb][2] = __ldcs((const int2*)(adjA + jb + 8));
        pa[kb][3] = __ldcs((const int2*)(adjB + jb + 8));
        ph0[kb] = *(const float2*)(g_h2 + jb);
        ph1[kb] = *(const float2*)(g_h2 + jb + 8);
    }
    #pragma unroll
    for (int q = 0; q < 4; q++) {
        CPA16(cdst[q],      csrc_h[q] + jbase);
        CPA16(cdst[q] + PL, csrc_l[q] + jbase);
    }
    CPCOMMIT();

    for (int t = 0; t < NTILES; t++) {
        const uint32_t curb = smem0 + (uint32_t)(t & 1) * BUFB;

        // ---- P fragments from prefetched adj/h2 ----
        uint32_t ahi[4][4], alo[4][4];
        #pragma unroll
        for (int kb = 0; kb < 4; kb++) {
            const float p00 = pexp(pa[kb][0].x, h1a + ph0[kb].x), p01 = pexp(pa[kb][0].y, h1a + ph0[kb].y);
            const float p10 = pexp(pa[kb][1].x, h1b + ph0[kb].x), p11 = pexp(pa[kb][1].y, h1b + ph0[kb].y);
            const float p02 = pexp(pa[kb][2].x, h1a + ph1[kb].x), p03 = pexp(pa[kb][2].y, h1a + ph1[kb].y);
            const float p12 = pexp(pa[kb][3].x, h1b + ph1[kb].x), p13 = pexp(pa[kb][3].y, h1b + ph1[kb].y);
            z0 += (p00 + p01) + (p02 + p03);
            z1 += (p10 + p11) + (p12 + p13);
            ahi[kb][0] = pack_hilo(p00, p01, alo[kb][0]);
            ahi[kb][1] = pack_hilo(p10, p11, alo[kb][1]);
            ahi[kb][2] = pack_hilo(p02, p03, alo[kb][2]);
            ahi[kb][3] = pack_hilo(p12, p13, alo[kb][3]);
        }

        // ---- prefetch next tile's adj/h2 (hidden under MMA phase) ----
        const int jn = (t + 1 < NTILES) ? jbase + (t + 1) * KT : jbase;
        #pragma unroll
        for (int kb = 0; kb < 4; kb++) {
            const int jb = jn + kb * 16 + jq;
            pa[kb][0] = __ldcs((const int2*)(adjA + jb));
            pa[kb][1] = __ldcs((const int2*)(adjB + jb));
            pa[kb][2] = __ldcs((const int2*)(adjA + jb + 8));
            pa[kb][3] = __ldcs((const int2*)(adjB + jb + 8));
            ph0[kb] = *(const float2*)(g_h2 + jb);
            ph1[kb] = *(const float2*)(g_h2 + jb + 8);
        }

        // ---- stage next H tile ----
        if (t + 1 < NTILES) {
            const uint32_t nxtb = (uint32_t)((t + 1) & 1) * BUFB;
            #pragma unroll
            for (int q = 0; q < 4; q++) {
                CPA16(cdst[q] + nxtb,      csrc_h[q] + jn);
                CPA16(cdst[q] + nxtb + PL, csrc_l[q] + jn);
            }
        }
        CPCOMMIT();
        CPWAIT1();
        __syncthreads();

        // ---- MMAs with ldmatrix B loads ----
        #pragma unroll
        for (int nb = 0; nb < 8; nb++) {
            const int rowc = nb * 8 + lmr;
            const uint32_t rowa = curb +
                (uint32_t)(rowc * 64 + (((lane >> 3) ^ lmr) * 8)) * 2;
            uint32_t bh[8], bl[8];
            LDM4(bh,     rowa);             // j 0..31
            LDM4(bh + 4, rowa ^ 64u);       // j 32..63 (seg+4 == XOR 64B)
            LDM4(bl,     rowa + PL);
            LDM4(bl + 4, (rowa + PL) ^ 64u);
            #pragma unroll
            for (int kb = 0; kb < 4; kb++) {
                MMA(acc[nb], ahi[kb], bh[2*kb], bh[2*kb+1]);
                MMA(acc[nb], alo[kb], bh[2*kb], bh[2*kb+1]);
                MMA(acc[nb], ahi[kb], bl[2*kb], bl[2*kb+1]);
            }
        }
        __syncthreads();
    }

    // ---- Z reduce across 4 lanes sharing a row ----
    z0 += __shfl_xor_sync(0xffffffffu, z0, 1);
    z0 += __shfl_xor_sync(0xffffffffu, z0, 2);
    z1 += __shfl_xor_sync(0xffffffffu, z1, 1);
    z1 += __shfl_xor_sync(0xffffffffu, z1, 2);
    if ((lane & 3) == 0) {
        g_Z[jsb*NN + g]     = z0;
        g_Z[jsb*NN + g + 8] = z1;
    }

    // ---- partial numerators ----
    #pragma unroll
    for (int nb = 0; nb < 8; nb++) {
        float2 v0; v0.x = acc[nb][0]; v0.y = acc[nb][1];
        float2 v1; v1.x = acc[nb][2]; v1.y = acc[nb][3];
        *(float2*)&g_acc[((size_t)jsb*NN + g    )*DD + nb*8 + jq] = v0;
        *(float2*)&g_acc[((size_t)jsb*NN + g + 8)*DD + nb*8 + jq] = v1;
    }
}

// ---------------- kernel 3: combine splits, normalize, ELU ----------------
__global__ void __launch_bounds__(256) combine_kernel(float* __restrict__ out) {
    const int gid = blockIdx.x * 256 + threadIdx.x;
    const int i = gid >> 6;
    float s = 0.f, z = 0.f;
    #pragma unroll
    for (int q = 0; q < JS; q++) {
        s += g_acc[(size_t)q*NN*DD + gid];
        z += g_Z[q*NN + i];
    }
    const float o = s / z;
    out[gid] = (o > 0.f) ? o : expm1f(o);
}

// ---------------- launcher ----------------
extern "C" void kernel_launch(void* const* d_in, const int* in_sizes, int n_in,
                              void* d_out, int out_size) {
    const float* features = (const float*)d_in[0];
    const int*   adj      = (const int*)d_in[1];
    const float* W        = (const float*)d_in[2];
    const float* a        = (const float*)d_in[3];
    float* out = (float*)d_out;

    gemm_fused_kernel<<<NN/16, 256>>>(features, W, a);
    attn_kernel<<<dim3(JS, NN/64), 128>>>(adj);
    combine_kernel<<<(NN*DD)/256, 256>>>(out);
}